// round 2
// baseline (speedup 1.0000x reference)
#include <cuda_runtime.h>
#include <cstdint>

// Problem constants
#define BB     8192
#define TT     64
#define FF     64
#define ORD    16
#define KK     256          // hidden units
#define RTOT   336          // F + ORD + K  (inner GEMM dim)
#define KC     16           // k-chunk
#define MT     64           // rows per CTA
#define NT     64           // hidden units per CTA
#define NTHREADS 256

// ---------------- persistent device state (no allocations allowed) ----------
__device__ float  g_hbuf[2u * BB * KK];          // double-buffered h (16 MB)
__device__ float  g_c[BB * KK];                  // cell state (8 MB)
__device__ float  g_yp[BB * ORD];                // feedback window
__device__ float4 g_Wp[RTOT * KK];               // gate-interleaved weights
__device__ float4 g_biasp[KK];                   // gate-interleaved bias

// ---------------- packed fp32x2 helpers (Blackwell dual-fp32) ---------------
__device__ __forceinline__ void fma2(unsigned long long& d,
                                     unsigned long long a,
                                     unsigned long long b) {
    asm("fma.rn.f32x2 %0, %1, %2, %0;" : "+l"(d) : "l"(a), "l"(b));
}
__device__ __forceinline__ unsigned long long bcast2(float v) {
    unsigned long long r;
    asm("mov.b64 %0, {%1, %2};" : "=l"(r) : "f"(v), "f"(v));
    return r;
}
__device__ __forceinline__ float2 unpack2(unsigned long long v) {
    float2 r;
    asm("mov.b64 {%0, %1}, %2;" : "=f"(r.x), "=f"(r.y) : "l"(v));
    return r;
}

__device__ __forceinline__ float sigmoidf_(float x) {
    return 1.0f / (1.0f + expf(-x));
}

// ---------------- init: zero state, load feedback window --------------------
__global__ void init_kernel(const float* __restrict__ y0) {
    int i = blockIdx.x * blockDim.x + threadIdx.x;
    int stride = gridDim.x * blockDim.x;
    for (int s = i; s < 2 * BB * KK; s += stride) g_hbuf[s] = 0.0f;
    for (int s = i; s < BB * KK; s += stride)     g_c[s]   = 0.0f;
    for (int s = i; s < BB * ORD; s += stride)    g_yp[s]  = y0[s];
}

// ---------------- repack weights: Wp[r][n] = (i,f,g,o) gates ----------------
__global__ void repack_kernel(const float* __restrict__ kern,   // [80, 1024]
                              const float* __restrict__ rec,    // [256, 1024]
                              const float* __restrict__ bias) { // [1024]
    int i = blockIdx.x * blockDim.x + threadIdx.x;
    int stride = gridDim.x * blockDim.x;
    for (int idx = i; idx < RTOT * KK; idx += stride) {
        int r = idx / KK;
        int n = idx - r * KK;
        float4 w;
        if (r < FF + ORD) {
            w.x = kern[r * 1024 + n];
            w.y = kern[r * 1024 + 256 + n];
            w.z = kern[r * 1024 + 512 + n];
            w.w = kern[r * 1024 + 768 + n];
        } else {
            int rr = r - (FF + ORD);
            w.x = rec[rr * 1024 + n];
            w.y = rec[rr * 1024 + 256 + n];
            w.z = rec[rr * 1024 + 512 + n];
            w.w = rec[rr * 1024 + 768 + n];
        }
        g_Wp[idx] = w;
    }
    for (int n = i; n < KK; n += stride) {
        float4 b;
        b.x = bias[n];
        b.y = bias[256 + n];
        b.z = bias[512 + n];
        b.w = bias[768 + n];
        g_biasp[n] = b;
    }
}

// ---------------- one LSTM timestep: fused GEMM + gates ---------------------
// grid: (B/MT = 128, K/NT = 4), block: 256 threads
// thread micro-tile: 4 rows x 4 hidden units x 4 gates
__global__ void __launch_bounds__(NTHREADS)
lstm_step(const float* __restrict__ x, int t, int parity) {
    __shared__ float  As[KC][MT + 1];   // +1 pad kills STS bank conflicts
    __shared__ float4 Ws[KC][NT];

    const int tid = threadIdx.x;
    const int tx  = tid & 15;           // hidden-unit group (strided by 16)
    const int ty  = tid >> 4;           // row group (strided by 16)
    const int mrow0 = blockIdx.x * MT;
    const int ncol0 = blockIdx.y * NT;

    const float* __restrict__ hprev = g_hbuf + (size_t)parity * BB * KK;
    float*       __restrict__ hnext = g_hbuf + (size_t)(parity ^ 1) * BB * KK;

    unsigned long long acc[4][4][2];    // [row][unit][gate-pair], each = 2 f32
    #pragma unroll
    for (int r = 0; r < 4; r++)
        #pragma unroll
        for (int j = 0; j < 4; j++) {
            acc[r][j][0] = 0ull;
            acc[r][j][1] = 0ull;
        }

    for (int kb = 0; kb < RTOT / KC; kb++) {
        // ---- stage A tile: 16 x 64 (k-major for broadcast) ----
        #pragma unroll
        for (int i = 0; i < 4; i++) {
            int s  = tid + i * NTHREADS;
            int kk = s & 15;
            int m  = s >> 4;
            int row = mrow0 + m;
            float v;
            if (kb < 4)        v = x[(size_t)row * (TT * FF) + t * FF + (kb * KC + kk)];
            else if (kb == 4)  v = g_yp[row * ORD + kk];
            else               v = hprev[(size_t)row * KK + ((kb - 5) * KC + kk)];
            As[kk][m] = v;
        }
        // ---- stage W tile: 16 x 64 float4 ----
        #pragma unroll
        for (int i = 0; i < 4; i++) {
            int s  = tid + i * NTHREADS;
            int kk = s >> 6;
            int n  = s & 63;
            Ws[kk][n] = g_Wp[(kb * KC + kk) * KK + ncol0 + n];
        }
        __syncthreads();

        // ---- compute ----
        #pragma unroll
        for (int kk = 0; kk < KC; kk++) {
            unsigned long long a2[4];
            #pragma unroll
            for (int r = 0; r < 4; r++)
                a2[r] = bcast2(As[kk][ty + 16 * r]);
            #pragma unroll
            for (int j = 0; j < 4; j++) {
                const ulonglong2 wv =
                    *reinterpret_cast<const ulonglong2*>(&Ws[kk][tx + 16 * j]);
                #pragma unroll
                for (int r = 0; r < 4; r++) {
                    fma2(acc[r][j][0], a2[r], wv.x);   // gates (i, f)
                    fma2(acc[r][j][1], a2[r], wv.y);   // gates (g, o)
                }
            }
        }
        __syncthreads();
    }

    // ---- epilogue: bias + gates + state update ----
    #pragma unroll
    for (int r = 0; r < 4; r++) {
        const int row = mrow0 + ty + 16 * r;
        #pragma unroll
        for (int j = 0; j < 4; j++) {
            const int n = ncol0 + tx + 16 * j;
            const float4 bp = g_biasp[n];
            float2 zif = unpack2(acc[r][j][0]);
            float2 zgo = unpack2(acc[r][j][1]);
            float gi = sigmoidf_(zif.x + bp.x);
            float gf = sigmoidf_(zif.y + bp.y);
            float gg = tanhf(zgo.x + bp.z);
            float go = sigmoidf_(zgo.y + bp.w);
            const size_t off = (size_t)row * KK + n;
            float cnew = gf * g_c[off] + gi * gg;
            float hnew = go * tanhf(cnew);
            g_c[off]   = cnew;
            hnext[off] = hnew;
        }
    }
}

// ---------------- finalize: pred = h_new @ dense_w + b; shift window --------
// one warp per batch row; deterministic (no atomics)
__global__ void finalize_kernel(float* __restrict__ out,
                                const float* __restrict__ dw,
                                const float* __restrict__ db,
                                int t, int parity) {
    const int warp = (blockIdx.x * blockDim.x + threadIdx.x) >> 5;
    const int lane = threadIdx.x & 31;
    if (warp >= BB) return;
    const float* h = g_hbuf + (size_t)(parity ^ 1) * BB * KK + (size_t)warp * KK;
    float s = 0.0f;
    #pragma unroll
    for (int i = 0; i < KK / 32; i++)
        s += h[lane + 32 * i] * dw[lane + 32 * i];
    #pragma unroll
    for (int off = 16; off >= 1; off >>= 1)
        s += __shfl_xor_sync(0xffffffffu, s, off);
    const float p = s + db[0];        // all lanes hold p

    float* yp = &g_yp[warp * ORD];
    float ypv = (lane < ORD - 1) ? yp[lane] : 0.0f;
    float up  = __shfl_up_sync(0xffffffffu, ypv, 1);
    if (lane == 0) {
        out[(size_t)warp * TT + t] = p;
        yp[0] = p;
    } else if (lane <= ORD - 1) {
        yp[lane] = up;                // yp[l] = old yp[l-1]
    }
}

// ---------------- launch ----------------------------------------------------
extern "C" void kernel_launch(void* const* d_in, const int* in_sizes, int n_in,
                              void* d_out, int out_size) {
    const float* x    = (const float*)d_in[0];  // [8192, 64, 64]
    const float* y0   = (const float*)d_in[1];  // [8192, 16]
    const float* kern = (const float*)d_in[2];  // [80, 1024]
    const float* rec  = (const float*)d_in[3];  // [256, 1024]
    const float* bias = (const float*)d_in[4];  // [1024]
    const float* dw   = (const float*)d_in[5];  // [256, 1]
    const float* db   = (const float*)d_in[6];  // [1]
    float* out = (float*)d_out;                 // [8192, 64, 1]

    init_kernel<<<2048, 256>>>(y0);
    repack_kernel<<<512, 256>>>(kern, rec, bias);

    dim3 grid(BB / MT, KK / NT);    // (128, 4)
    for (int t = 0; t < TT; t++) {
        lstm_step<<<grid, NTHREADS>>>(x, t, t & 1);
        finalize_kernel<<<BB * 32 / 256, 256>>>(out, dw, db, t, t & 1);
    }
}